// round 16
// baseline (speedup 1.0000x reference)
#include <cuda_runtime.h>
#include <cuda_fp16.h>
#include <cstdint>
#include <cstring>

// Problem constants
#define DDIM   4096
#define TOPK   2048
#define NMASK  64
#define PBOUND 1024
#define MDIM   4096      // B*S
#define NDIM   4096      // O

// GEMM tiling: 128x128x32 fp16 single-term, 4-stage cp.async, 2 CTAs/SM
#define BM 128
#define BN 128
#define BK 32
#define STAGES 4
#define TILE_B (BM * BK * 2)           // 8192 bytes per fp16 tile (128 x 32)
#define STAGE_B (2 * TILE_B)           // A, W = 16384
#define SMEM_TOTAL (STAGES * STAGE_B)  // 65536 (x2 CTAs = 128KB < 228KB)

// ---------------------------------------------------------------------------
// Device-global scratch (allocation-free rule)
// ---------------------------------------------------------------------------
__device__ int g_pcnt[4 * DDIM];        // partial rank counts (4 e-ranges)
__device__ int g_done;                  // last-block counter (reset each run)
__device__ int g_perm_mode;             // 8 = int64 storage, 4 = int32
__device__ int g_mask_mode;             // 1 = uint8, 4 = int32, 5 = float32
__device__ __align__(16) int g_kidx[DDIM];  // compacted active K indices
__device__ int g_kpad;                  // active count padded to BK
__device__ int g_kcnt;                  // exact active count
__device__ __align__(16) __half g_Af[(size_t)MDIM * DDIM];
__device__ __align__(16) __half g_Wf[(size_t)NDIM * DDIM];

// ---------------------------------------------------------------------------
// PTX helpers (baseline sm_80+ features only)
// ---------------------------------------------------------------------------
__device__ __forceinline__ uint32_t smem_u32(const void* p) {
    uint32_t a;
    asm("{ .reg .u64 t; cvta.to.shared.u64 t, %1; cvt.u32.u64 %0, t; }"
        : "=r"(a) : "l"(p));
    return a;
}
__device__ __forceinline__ void cp16(uint32_t dst, const void* src) {
    asm volatile("cp.async.cg.shared.global [%0], [%1], 16;"
                 :: "r"(dst), "l"(src) : "memory");
}
__device__ __forceinline__ void cp_commit() {
    asm volatile("cp.async.commit_group;" ::: "memory");
}
template <int N>
__device__ __forceinline__ void cp_wait() {
    asm volatile("cp.async.wait_group %0;" :: "n"(N) : "memory");
}
__device__ __forceinline__ void ldsm4(uint32_t* r, uint32_t addr) {
    asm volatile("ldmatrix.sync.aligned.m8n8.x4.shared.b16 {%0,%1,%2,%3}, [%4];"
                 : "=r"(r[0]), "=r"(r[1]), "=r"(r[2]), "=r"(r[3]) : "r"(addr));
}
__device__ __forceinline__ void mma_f16(float* c, const uint32_t* a,
                                        uint32_t b0, uint32_t b1) {
    asm volatile(
        "mma.sync.aligned.m16n8k16.row.col.f32.f16.f16.f32 "
        "{%0,%1,%2,%3}, {%4,%5,%6,%7}, {%8,%9}, {%0,%1,%2,%3};"
        : "+f"(c[0]), "+f"(c[1]), "+f"(c[2]), "+f"(c[3])
        : "r"(a[0]), "r"(a[1]), "r"(a[2]), "r"(a[3]), "r"(b0), "r"(b1));
}
// Swizzled byte offset inside a 128x32-fp16 tile (64B rows, 4x16B chunks).
__device__ __forceinline__ uint32_t tile_off(int row, int chunk) {
    return (uint32_t)row * 64u + (uint32_t)((chunk ^ ((row >> 1) & 3)) * 16);
}

__device__ __forceinline__ int mask_at(const void* masks, int mode, size_t idx) {
    if (mode == 1) return ((const unsigned char*)masks)[idx] != 0;
    if (mode == 4) return ((const int*)masks)[idx] != 0;
    return ((const float*)masks)[idx] != 0.0f;
}

// ---------------------------------------------------------------------------
// Kernel 1 (fused): blocks 0..63 compute partial top-k rank counts; block 64
// runs dtype detection, waits for the 64 partials (all 65 blocks co-resident
// on 148 SMs), then does mask selection + gate + K compaction.
// ---------------------------------------------------------------------------
__global__ void __launch_bounds__(1024, 1)
prep_select_kernel(const float* __restrict__ x,
                   const void* __restrict__ perm,
                   const void* __restrict__ masks) {
    const int tid = threadIdx.x;

    if (blockIdx.x < 64) {
        // ---- partial rank counts (uses only 256 threads of the block)
        __shared__ float a[1024];
        const int dblk = blockIdx.x & 15;        // d-range selector
        const int eh = blockIdx.x >> 4;          // e-range selector 0..3
        const int ebase = eh * 1024;
        const float* f0 = x + (size_t)PBOUND * DDIM;

        for (int i = tid; i < 1024; i += blockDim.x) a[i] = fabsf(f0[ebase + i]);
        __syncthreads();

        if (tid < 256) {
            int d = dblk * 256 + tid;
            float ad = fabsf(f0[d]);
            int cnt = 0;
#pragma unroll 8
            for (int el = 0; el < 1024; el++) {
                float ae = a[el];
                int e = ebase + el;
                cnt += (int)((ae > ad) || (ae == ad && e < d));
            }
            g_pcnt[eh * DDIM + d] = cnt;
        }
        __syncthreads();
        __threadfence();
        if (tid == 0) atomicAdd(&g_done, 1);
        return;
    }

    // ---- block 64: detect + wait + select
    __shared__ int counts[NMASK];
    __shared__ unsigned int abm[128];        // 4096-bit active bitmap
    __shared__ int sbest, sflag;
    __shared__ int wsum[32];
    __shared__ int s_inactive;
    __shared__ int s_pmode, s_mmode;

    const int wid = tid >> 5, lane = tid & 31;

    // dtype detection (first 256 threads)
    if (tid < 256) {
        const int* p32 = (const int*)perm;
        int zeros = 0;
        for (int i = 1 + 2 * tid; i < 4096; i += 512) zeros += (p32[i] == 0);

        const unsigned int* m32 = (const unsigned int*)masks;
        int has_f32 = 0;
        unsigned int maxv = 0;
        for (int i = tid; i < 1024; i += 256) {
            unsigned int v = m32[i];
            if (v == 0x3F800000u) has_f32 = 1;
            if (v > maxv) maxv = v;
        }
#pragma unroll
        for (int off = 16; off > 0; off >>= 1) {
            zeros   += __shfl_down_sync(0xffffffffu, zeros, off);
            has_f32 |= __shfl_down_sync(0xffffffffu, has_f32, off);
            unsigned int o = __shfl_down_sync(0xffffffffu, maxv, off);
            if (o > maxv) maxv = o;
        }
        if (lane == 0) {
            counts[wid * 3 + 0] = zeros;
            counts[wid * 3 + 1] = has_f32;
            counts[wid * 3 + 2] = (int)maxv;
        }
    }
    __syncthreads();
    if (tid == 0) {
        int z = 0, f = 0;
        unsigned int mx = 0;
        for (int i = 0; i < 8; i++) {
            z += counts[i * 3 + 0];
            f |= counts[i * 3 + 1];
            unsigned int m = (unsigned int)counts[i * 3 + 2];
            if (m > mx) mx = m;
        }
        s_pmode = g_perm_mode = (z >= 1000) ? 8 : 4;
        s_mmode = g_mask_mode = f ? 5 : (mx <= 1u ? 4 : 1);
        while (atomicAdd(&g_done, 0) < 64) { }
        g_done = 0;                       // reset for next graph replay
        s_inactive = 0x7FFFFFFF;
    }
    __syncthreads();
    __threadfence();   // acquire g_pcnt writes

    const int pmode = s_pmode, mmode = s_mmode;

    if (tid < 128) abm[tid] = 0u;
    __syncthreads();

    // topk flags (sum of 4 partial counts) -> permuted active bitmap
    const int d0 = tid * 4;
#pragma unroll
    for (int q = 0; q < 4; q++) {
        int d = d0 + q;
        int cnt = g_pcnt[d] + g_pcnt[DDIM + d] + g_pcnt[2 * DDIM + d] +
                  g_pcnt[3 * DDIM + d];
        if (cnt < TOPK) {
            int p = (pmode == 8) ? (int)((const long long*)perm)[d]
                                 : ((const int*)perm)[d];
            atomicOr(&abm[p >> 5], 1u << (p & 31));
        }
    }
    __syncthreads();

    // counts[j] = popcount(mask_j AND active); warp w handles rows 2w, 2w+1.
    // Batched 4-wide for MLP: 4 independent loads per step, then 4 ballots.
#pragma unroll
    for (int r = 0; r < 2; r++) {
        const int j = wid * 2 + r;
        int tot = 0;
        for (int it = 0; it < 128; it += 4) {
            int b0 = mask_at(masks, mmode, (size_t)j * DDIM + (it + 0) * 32 + lane);
            int b1 = mask_at(masks, mmode, (size_t)j * DDIM + (it + 1) * 32 + lane);
            int b2 = mask_at(masks, mmode, (size_t)j * DDIM + (it + 2) * 32 + lane);
            int b3 = mask_at(masks, mmode, (size_t)j * DDIM + (it + 3) * 32 + lane);
            unsigned int w0 = __ballot_sync(0xffffffffu, b0);
            unsigned int w1 = __ballot_sync(0xffffffffu, b1);
            unsigned int w2 = __ballot_sync(0xffffffffu, b2);
            unsigned int w3 = __ballot_sync(0xffffffffu, b3);
            tot += __popc(w0 & abm[it + 0]);
            tot += __popc(w1 & abm[it + 1]);
            tot += __popc(w2 & abm[it + 2]);
            tot += __popc(w3 & abm[it + 3]);
        }
        if (lane == 0) counts[j] = tot;
    }
    __syncthreads();

    if (tid == 0) {
        int best = 0, bc = counts[0];
        for (int jj = 1; jj < NMASK; jj++)
            if (counts[jj] > bc) { bc = counts[jj]; best = jj; }
        sbest = best;
        sflag = ((float)bc / (float)TOPK >= 0.3f) ? 1 : 0;
    }
    __syncthreads();

    const int best = sbest, flag = sflag;

    // per-thread 4 consecutive columns of the chosen mask
    int act[4], s = 0;
#pragma unroll
    for (int q = 0; q < 4; q++) {
        int a = flag && mask_at(masks, mmode, (size_t)best * DDIM + d0 + q);
        act[q] = a;
        s += a;
    }
#pragma unroll
    for (int q = 0; q < 4; q++)
        if (!act[q]) { atomicMin(&s_inactive, d0 + q); break; }

    // inclusive shuffle scan of s over 1024 threads (2 barriers total)
    int v = s;
#pragma unroll
    for (int off = 1; off < 32; off <<= 1) {
        int n = __shfl_up_sync(0xffffffffu, v, off);
        if (lane >= off) v += n;
    }
    if (lane == 31) wsum[wid] = v;
    __syncthreads();
    if (wid == 0) {
        int wv = wsum[lane];
#pragma unroll
        for (int off = 1; off < 32; off <<= 1) {
            int n = __shfl_up_sync(0xffffffffu, wv, off);
            if (lane >= off) wv += n;
        }
        wsum[lane] = wv;
    }
    __syncthreads();
    int base = (wid > 0) ? wsum[wid - 1] : 0;
    int pos = base + v - s;
#pragma unroll
    for (int q = 0; q < 4; q++)
        if (act[q]) g_kidx[pos++] = d0 + q;
    __syncthreads();

    if (tid == 0) {
        int cnt = wsum[31];
        int kpad = (cnt + BK - 1) / BK * BK;
        int dummy = (s_inactive == 0x7FFFFFFF) ? 0 : s_inactive;  // inactive col
        for (int q = cnt; q < kpad; q++) g_kidx[q] = dummy;
        g_kpad = kpad;
        g_kcnt = cnt;
    }
}

// ---------------------------------------------------------------------------
// Kernel 2: gathered f32 -> fp16 conversion for BOTH X and W (compacted K).
// ---------------------------------------------------------------------------
__device__ __forceinline__ uint32_t pack_half2(float a, float b) {
    __half2 h = __floats2half2_rn(a, b);
    uint32_t u; memcpy(&u, &h, 4); return u;
}

__global__ void convert_kernel(const float* __restrict__ x,
                               const float* __restrict__ w) {
    const int kpad = g_kpad, kcnt = g_kcnt;
    size_t i = (size_t)blockIdx.x * blockDim.x + threadIdx.x;
    int row_id = (int)(i >> 10);        // 0..(MDIM+NDIM-1)
    int jc = ((int)i & 1023) * 4;
    if (jc >= kpad) return;
    int4 kk = ((const int4*)g_kidx)[jc >> 2];

    uint2 v;
    if (row_id < MDIM) {
        const float* row = x + (size_t)row_id * DDIM;
        float v0 = (jc + 0 < kcnt) ? row[kk.x] : 0.0f;
        float v1 = (jc + 1 < kcnt) ? row[kk.y] : 0.0f;
        float v2 = (jc + 2 < kcnt) ? row[kk.z] : 0.0f;
        float v3 = (jc + 3 < kcnt) ? row[kk.w] : 0.0f;
        v.x = pack_half2(v0, v1);
        v.y = pack_half2(v2, v3);
        *(uint2*)(g_Af + (size_t)row_id * DDIM + jc) = v;
    } else {
        const float* row = w + (size_t)(row_id - MDIM) * DDIM;
        v.x = pack_half2(row[kk.x], row[kk.y]);
        v.y = pack_half2(row[kk.z], row[kk.w]);
        *(uint2*)(g_Wf + (size_t)(row_id - MDIM) * DDIM + jc) = v;
    }
}

// ---------------------------------------------------------------------------
// Kernel 3: warp-MMA fp16 single-term GEMM over compacted K (R11-proven).
// 128x128x32 CTA tile, 8 warps (2x4), warp tile 64x32, 4-stage cp.async,
// 2 CTAs/SM. B frags hoisted per tile; A frags software-pipelined in pairs.
// ---------------------------------------------------------------------------
__global__ void __launch_bounds__(256, 2)
gemm_mma_kernel(float* __restrict__ C) {
    extern __shared__ char smem[];
    const uint32_t sb = smem_u32(smem);
    const int tid = threadIdx.x;
    const int wid = tid >> 5;
    const int lane = tid & 31;
    const int warp_m = wid & 1;
    const int warp_n = wid >> 1;

    const int m0 = blockIdx.y * BM;
    const int n0 = blockIdx.x * BN;
    const int NT = g_kpad / BK;          // dynamic k-tile count

    const int lr = tid >> 2;             // 0..63
    const int lch = tid & 3;             // 16B chunk
    const int lc = lch * 8;

    const __half* A = g_Af + (size_t)m0 * DDIM;
    const __half* W = g_Wf + (size_t)n0 * DDIM;

#define LOAD_STAGE(base, kb)                                                   \
    do {                                                                       \
        const __half* sa = A + (size_t)lr * DDIM + (kb) + lc;                  \
        const __half* sw = W + (size_t)lr * DDIM + (kb) + lc;                  \
        cp16((base) + tile_off(lr, lch), sa);                                  \
        cp16((base) + tile_off(lr + 64, lch), sa + (size_t)64 * DDIM);         \
        cp16((base) + TILE_B + tile_off(lr, lch), sw);                         \
        cp16((base) + TILE_B + tile_off(lr + 64, lch), sw + (size_t)64 * DDIM);\
    } while (0)

    // prologue: stages 0..STAGES-2 (guarded for short K)
#pragma unroll
    for (int it = 0; it < STAGES - 1; ++it) {
        if (it < NT) LOAD_STAGE(sb + it * STAGE_B, it * BK);
        cp_commit();
    }

    float acc[4][4][4];
#pragma unroll
    for (int mi = 0; mi < 4; mi++)
#pragma unroll
        for (int nj = 0; nj < 4; nj++)
#pragma unroll
            for (int q = 0; q < 4; q++) acc[mi][nj][q] = 0.0f;

    const int ar = warp_m * 64 + (lane & 15);
    const int br = warp_n * 32 + (lane & 15);
    const int kgrp = lane >> 4;

#pragma unroll 1
    for (int it = 0; it < NT; ++it) {
        cp_wait<STAGES - 2>();
        __syncthreads();   // stage(it) ready; all warps done with old buffer

        if (it + STAGES - 1 < NT)
            LOAD_STAGE(sb + ((it + STAGES - 1) & (STAGES - 1)) * STAGE_B,
                       (it + STAGES - 1) * BK);
        cp_commit();

        const uint32_t stg = sb + (it & (STAGES - 1)) * STAGE_B;

        // hoist ALL B fragments for this 32-K tile (4 x ldsm4 = 16 regs)
        uint32_t bfr[4][4];
#pragma unroll
        for (int g = 0; g < 2; g++)
#pragma unroll
            for (int ni = 0; ni < 2; ni++)
                ldsm4(bfr[g * 2 + ni],
                      stg + TILE_B + tile_off(br + ni * 16, g * 2 + kgrp));

        // A fragments: 4 pipeline steps of (g, mi-pair), double-buffered
        uint32_t af[2][2][4];
#pragma unroll
        for (int q = 0; q < 2; q++)
            ldsm4(af[0][q], stg + tile_off(ar + q * 16, kgrp));   // (g=0,mp=0)

#pragma unroll
        for (int s = 0; s < 4; s++) {
            const int g = s >> 1, mp = s & 1, buf = s & 1;
            if (s < 3) {
                const int ng = (s + 1) >> 1, nmp = (s + 1) & 1;
#pragma unroll
                for (int q = 0; q < 2; q++)
                    ldsm4(af[buf ^ 1][q],
                          stg + tile_off(ar + (nmp * 2 + q) * 16, ng * 2 + kgrp));
            }
#pragma unroll
            for (int q = 0; q < 2; q++) {
                const int mi = mp * 2 + q;
#pragma unroll
                for (int nj = 0; nj < 4; nj++) {
                    const int ni = nj >> 1, sub = nj & 1;
                    mma_f16(acc[mi][nj], af[buf][q],
                            bfr[g * 2 + ni][sub], bfr[g * 2 + ni][sub + 2]);
                }
            }
        }
    }

    // epilogue: always write (zeros when gate is off / NT==0)
    const int crow = m0 + warp_m * 64 + (lane >> 2);
    const int ccol = n0 + warp_n * 32 + (lane & 3) * 2;
#pragma unroll
    for (int mi = 0; mi < 4; mi++) {
#pragma unroll
        for (int nj = 0; nj < 4; nj++) {
            float* p0 = C + (size_t)(crow + mi * 16) * NDIM + ccol + nj * 8;
            float* p1 = p0 + (size_t)8 * NDIM;
            *(float2*)p0 = make_float2(acc[mi][nj][0], acc[mi][nj][1]);
            *(float2*)p1 = make_float2(acc[mi][nj][2], acc[mi][nj][3]);
        }
    }
#undef LOAD_STAGE
}

// ---------------------------------------------------------------------------
// Launch
// ---------------------------------------------------------------------------
extern "C" void kernel_launch(void* const* d_in, const int* in_sizes, int n_in,
                              void* d_out, int out_size) {
    const float* x     = (const float*)d_in[0];
    const float* w     = (const float*)d_in[1];
    const void*  masks = d_in[2];
    const void*  perm  = d_in[3];
    float*       out   = (float*)d_out;

    cudaFuncSetAttribute(gemm_mma_kernel,
                         cudaFuncAttributeMaxDynamicSharedMemorySize, SMEM_TOTAL);

    prep_select_kernel<<<65, 1024>>>(x, perm, masks);
    convert_kernel<<<((MDIM + NDIM) * 1024) / 256, 256>>>(x, w);

    dim3 grid(NDIM / BN, MDIM / BM);   // (32, 32)
    gemm_mma_kernel<<<grid, 256, SMEM_TOTAL>>>(out);
}

// round 17
// speedup vs baseline: 1.0303x; 1.0303x over previous
#include <cuda_runtime.h>
#include <cuda_fp16.h>
#include <cstdint>
#include <cstring>

// Problem constants
#define DDIM   4096
#define TOPK   2048
#define NMASK  64
#define PBOUND 1024
#define MDIM   4096      // B*S
#define NDIM   4096      // O

// GEMM tiling: 128x128x32 fp16 single-term, 4-stage cp.async, 2 CTAs/SM
#define BM 128
#define BN 128
#define BK 32
#define STAGES 4
#define TILE_B (BM * BK * 2)           // 8192 bytes per fp16 tile (128 x 32)
#define STAGE_B (2 * TILE_B)           // A, W = 16384
#define SMEM_TOTAL (STAGES * STAGE_B)  // 65536 (x2 CTAs = 128KB < 228KB)

#define NEH 8                           // e-range splits for rank counting
#define NPREP (NEH * 16)                // 128 partial blocks

// ---------------------------------------------------------------------------
// Device-global scratch (allocation-free rule)
// ---------------------------------------------------------------------------
__device__ int g_pcnt[NEH * DDIM];      // partial rank counts (8 e-ranges)
__device__ int g_done;                  // last-block counter (reset each run)
__device__ int g_perm_mode;             // 8 = int64 storage, 4 = int32
__device__ int g_mask_mode;             // 1 = uint8, 4 = int32, 5 = float32
__device__ __align__(16) int g_kidx[DDIM];  // compacted active K indices
__device__ int g_kpad;                  // active count padded to BK
__device__ int g_kcnt;                  // exact active count
__device__ __align__(16) __half g_Af[(size_t)MDIM * DDIM];
__device__ __align__(16) __half g_Wf[(size_t)NDIM * DDIM];

// ---------------------------------------------------------------------------
// PTX helpers (baseline sm_80+ features only)
// ---------------------------------------------------------------------------
__device__ __forceinline__ uint32_t smem_u32(const void* p) {
    uint32_t a;
    asm("{ .reg .u64 t; cvta.to.shared.u64 t, %1; cvt.u32.u64 %0, t; }"
        : "=r"(a) : "l"(p));
    return a;
}
__device__ __forceinline__ void cp16(uint32_t dst, const void* src) {
    asm volatile("cp.async.cg.shared.global [%0], [%1], 16;"
                 :: "r"(dst), "l"(src) : "memory");
}
__device__ __forceinline__ void cp_commit() {
    asm volatile("cp.async.commit_group;" ::: "memory");
}
template <int N>
__device__ __forceinline__ void cp_wait() {
    asm volatile("cp.async.wait_group %0;" :: "n"(N) : "memory");
}
__device__ __forceinline__ void ldsm4(uint32_t* r, uint32_t addr) {
    asm volatile("ldmatrix.sync.aligned.m8n8.x4.shared.b16 {%0,%1,%2,%3}, [%4];"
                 : "=r"(r[0]), "=r"(r[1]), "=r"(r[2]), "=r"(r[3]) : "r"(addr));
}
__device__ __forceinline__ void mma_f16(float* c, const uint32_t* a,
                                        uint32_t b0, uint32_t b1) {
    asm volatile(
        "mma.sync.aligned.m16n8k16.row.col.f32.f16.f16.f32 "
        "{%0,%1,%2,%3}, {%4,%5,%6,%7}, {%8,%9}, {%0,%1,%2,%3};"
        : "+f"(c[0]), "+f"(c[1]), "+f"(c[2]), "+f"(c[3])
        : "r"(a[0]), "r"(a[1]), "r"(a[2]), "r"(a[3]), "r"(b0), "r"(b1));
}
// Swizzled byte offset inside a 128x32-fp16 tile (64B rows, 4x16B chunks).
__device__ __forceinline__ uint32_t tile_off(int row, int chunk) {
    return (uint32_t)row * 64u + (uint32_t)((chunk ^ ((row >> 1) & 3)) * 16);
}

__device__ __forceinline__ int mask_at(const void* masks, int mode, size_t idx) {
    if (mode == 1) return ((const unsigned char*)masks)[idx] != 0;
    if (mode == 4) return ((const int*)masks)[idx] != 0;
    return ((const float*)masks)[idx] != 0.0f;
}

// ---------------------------------------------------------------------------
// Kernel 1 (fused): blocks 0..127 compute partial top-k rank counts
// (16 d-blocks x 8 e-ranges, all 1024 threads active); block 128 runs dtype
// detection, waits for the partials (129 blocks co-resident on 148 SMs),
// then does mask selection + gate + K compaction.
// ---------------------------------------------------------------------------
__global__ void __launch_bounds__(1024, 1)
prep_select_kernel(const float* __restrict__ x,
                   const void* __restrict__ perm,
                   const void* __restrict__ masks) {
    const int tid = threadIdx.x;

    if (blockIdx.x < NPREP) {
        // ---- partial rank counts: 256 d x 512 e per block, 1024 threads
        __shared__ float a[512];
        __shared__ int part[4][256];
        const int dblk = blockIdx.x & 15;        // d-range selector 0..15
        const int eh = blockIdx.x >> 4;          // e-range selector 0..7
        const int ebase = eh * 512;
        const float* f0 = x + (size_t)PBOUND * DDIM;

        if (tid < 512) a[tid] = fabsf(f0[ebase + tid]);
        __syncthreads();

        const int sub = tid >> 8;                // e-subrange 0..3 (128 e each)
        const int dt = tid & 255;                // d within block
        const int d = dblk * 256 + dt;
        const float ad = fabsf(f0[d]);
        const int e0 = sub * 128;
        int cnt = 0;
#pragma unroll 8
        for (int el = 0; el < 128; el++) {
            float ae = a[e0 + el];
            int e = ebase + e0 + el;
            cnt += (int)((ae > ad) || (ae == ad && e < d));
        }
        part[sub][dt] = cnt;
        __syncthreads();
        if (tid < 256)
            g_pcnt[eh * DDIM + dblk * 256 + tid] =
                part[0][tid] + part[1][tid] + part[2][tid] + part[3][tid];
        __syncthreads();
        __threadfence();
        if (tid == 0) atomicAdd(&g_done, 1);
        return;
    }

    // ---- block NPREP: detect + wait + select
    __shared__ int counts[NMASK];
    __shared__ unsigned int abm[128];        // 4096-bit active bitmap
    __shared__ int sbest, sflag;
    __shared__ int wsum[32];
    __shared__ int s_inactive;
    __shared__ int s_pmode, s_mmode;

    const int wid = tid >> 5, lane = tid & 31;

    // dtype detection (first 256 threads)
    if (tid < 256) {
        const int* p32 = (const int*)perm;
        int zeros = 0;
        for (int i = 1 + 2 * tid; i < 4096; i += 512) zeros += (p32[i] == 0);

        const unsigned int* m32 = (const unsigned int*)masks;
        int has_f32 = 0;
        unsigned int maxv = 0;
        for (int i = tid; i < 1024; i += 256) {
            unsigned int v = m32[i];
            if (v == 0x3F800000u) has_f32 = 1;
            if (v > maxv) maxv = v;
        }
#pragma unroll
        for (int off = 16; off > 0; off >>= 1) {
            zeros   += __shfl_down_sync(0xffffffffu, zeros, off);
            has_f32 |= __shfl_down_sync(0xffffffffu, has_f32, off);
            unsigned int o = __shfl_down_sync(0xffffffffu, maxv, off);
            if (o > maxv) maxv = o;
        }
        if (lane == 0) {
            counts[wid * 3 + 0] = zeros;
            counts[wid * 3 + 1] = has_f32;
            counts[wid * 3 + 2] = (int)maxv;
        }
    }
    __syncthreads();
    if (tid == 0) {
        int z = 0, f = 0;
        unsigned int mx = 0;
        for (int i = 0; i < 8; i++) {
            z += counts[i * 3 + 0];
            f |= counts[i * 3 + 1];
            unsigned int m = (unsigned int)counts[i * 3 + 2];
            if (m > mx) mx = m;
        }
        s_pmode = g_perm_mode = (z >= 1000) ? 8 : 4;
        s_mmode = g_mask_mode = f ? 5 : (mx <= 1u ? 4 : 1);
        while (atomicAdd(&g_done, 0) < NPREP) { }
        g_done = 0;                       // reset for next graph replay
        s_inactive = 0x7FFFFFFF;
    }
    __syncthreads();
    __threadfence();   // acquire g_pcnt writes

    const int pmode = s_pmode, mmode = s_mmode;

    if (tid < 128) abm[tid] = 0u;
    __syncthreads();

    // topk flags (sum of 8 partial counts) -> permuted active bitmap
    const int d0 = tid * 4;
#pragma unroll
    for (int q = 0; q < 4; q++) {
        int d = d0 + q;
        int cnt = 0;
#pragma unroll
        for (int h = 0; h < NEH; h++) cnt += g_pcnt[h * DDIM + d];
        if (cnt < TOPK) {
            int p = (pmode == 8) ? (int)((const long long*)perm)[d]
                                 : ((const int*)perm)[d];
            atomicOr(&abm[p >> 5], 1u << (p & 31));
        }
    }
    __syncthreads();

    // counts[j] = popcount(mask_j AND active); warp w handles rows 2w, 2w+1.
#pragma unroll
    for (int r = 0; r < 2; r++) {
        const int j = wid * 2 + r;
        int tot = 0;
        for (int it = 0; it < 128; it++) {
            int p = it * 32 + lane;
            int bit = mask_at(masks, mmode, (size_t)j * DDIM + p);
            unsigned int word = __ballot_sync(0xffffffffu, bit);
            tot += __popc(word & abm[it]);
        }
        if (lane == 0) counts[j] = tot;
    }
    __syncthreads();

    if (tid == 0) {
        int best = 0, bc = counts[0];
        for (int jj = 1; jj < NMASK; jj++)
            if (counts[jj] > bc) { bc = counts[jj]; best = jj; }
        sbest = best;
        sflag = ((float)bc / (float)TOPK >= 0.3f) ? 1 : 0;
    }
    __syncthreads();

    const int best = sbest, flag = sflag;

    // per-thread 4 consecutive columns of the chosen mask
    int act[4], s = 0;
#pragma unroll
    for (int q = 0; q < 4; q++) {
        int a = flag && mask_at(masks, mmode, (size_t)best * DDIM + d0 + q);
        act[q] = a;
        s += a;
    }
#pragma unroll
    for (int q = 0; q < 4; q++)
        if (!act[q]) { atomicMin(&s_inactive, d0 + q); break; }

    // inclusive shuffle scan of s over 1024 threads (2 barriers total)
    int v = s;
#pragma unroll
    for (int off = 1; off < 32; off <<= 1) {
        int n = __shfl_up_sync(0xffffffffu, v, off);
        if (lane >= off) v += n;
    }
    if (lane == 31) wsum[wid] = v;
    __syncthreads();
    if (wid == 0) {
        int wv = wsum[lane];
#pragma unroll
        for (int off = 1; off < 32; off <<= 1) {
            int n = __shfl_up_sync(0xffffffffu, wv, off);
            if (lane >= off) wv += n;
        }
        wsum[lane] = wv;
    }
    __syncthreads();
    int base = (wid > 0) ? wsum[wid - 1] : 0;
    int pos = base + v - s;
#pragma unroll
    for (int q = 0; q < 4; q++)
        if (act[q]) g_kidx[pos++] = d0 + q;
    __syncthreads();

    if (tid == 0) {
        int cnt = wsum[31];
        int kpad = (cnt + BK - 1) / BK * BK;
        int dummy = (s_inactive == 0x7FFFFFFF) ? 0 : s_inactive;  // inactive col
        for (int q = cnt; q < kpad; q++) g_kidx[q] = dummy;
        g_kpad = kpad;
        g_kcnt = cnt;
    }
}

// ---------------------------------------------------------------------------
// Kernel 2: gathered f32 -> fp16 conversion for BOTH X and W (compacted K).
// ---------------------------------------------------------------------------
__device__ __forceinline__ uint32_t pack_half2(float a, float b) {
    __half2 h = __floats2half2_rn(a, b);
    uint32_t u; memcpy(&u, &h, 4); return u;
}

__global__ void convert_kernel(const float* __restrict__ x,
                               const float* __restrict__ w) {
    const int kpad = g_kpad, kcnt = g_kcnt;
    size_t i = (size_t)blockIdx.x * blockDim.x + threadIdx.x;
    int row_id = (int)(i >> 10);        // 0..(MDIM+NDIM-1)
    int jc = ((int)i & 1023) * 4;
    if (jc >= kpad) return;
    int4 kk = ((const int4*)g_kidx)[jc >> 2];

    uint2 v;
    if (row_id < MDIM) {
        const float* row = x + (size_t)row_id * DDIM;
        float v0 = (jc + 0 < kcnt) ? row[kk.x] : 0.0f;
        float v1 = (jc + 1 < kcnt) ? row[kk.y] : 0.0f;
        float v2 = (jc + 2 < kcnt) ? row[kk.z] : 0.0f;
        float v3 = (jc + 3 < kcnt) ? row[kk.w] : 0.0f;
        v.x = pack_half2(v0, v1);
        v.y = pack_half2(v2, v3);
        *(uint2*)(g_Af + (size_t)row_id * DDIM + jc) = v;
    } else {
        const float* row = w + (size_t)(row_id - MDIM) * DDIM;
        v.x = pack_half2(row[kk.x], row[kk.y]);
        v.y = pack_half2(row[kk.z], row[kk.w]);
        *(uint2*)(g_Wf + (size_t)(row_id - MDIM) * DDIM + jc) = v;
    }
}

// ---------------------------------------------------------------------------
// Kernel 3: warp-MMA fp16 single-term GEMM over compacted K (R11-proven).
// 128x128x32 CTA tile, 8 warps (2x4), warp tile 64x32, 4-stage cp.async,
// 2 CTAs/SM. B frags hoisted per tile; A frags software-pipelined in pairs.
// ---------------------------------------------------------------------------
__global__ void __launch_bounds__(256, 2)
gemm_mma_kernel(float* __restrict__ C) {
    extern __shared__ char smem[];
    const uint32_t sb = smem_u32(smem);
    const int tid = threadIdx.x;
    const int wid = tid >> 5;
    const int lane = tid & 31;
    const int warp_m = wid & 1;
    const int warp_n = wid >> 1;

    const int m0 = blockIdx.y * BM;
    const int n0 = blockIdx.x * BN;
    const int NT = g_kpad / BK;          // dynamic k-tile count

    const int lr = tid >> 2;             // 0..63
    const int lch = tid & 3;             // 16B chunk
    const int lc = lch * 8;

    const __half* A = g_Af + (size_t)m0 * DDIM;
    const __half* W = g_Wf + (size_t)n0 * DDIM;

#define LOAD_STAGE(base, kb)                                                   \
    do {                                                                       \
        const __half* sa = A + (size_t)lr * DDIM + (kb) + lc;                  \
        const __half* sw = W + (size_t)lr * DDIM + (kb) + lc;                  \
        cp16((base) + tile_off(lr, lch), sa);                                  \
        cp16((base) + tile_off(lr + 64, lch), sa + (size_t)64 * DDIM);         \
        cp16((base) + TILE_B + tile_off(lr, lch), sw);                         \
        cp16((base) + TILE_B + tile_off(lr + 64, lch), sw + (size_t)64 * DDIM);\
    } while (0)

    // prologue: stages 0..STAGES-2 (guarded for short K)
#pragma unroll
    for (int it = 0; it < STAGES - 1; ++it) {
        if (it < NT) LOAD_STAGE(sb + it * STAGE_B, it * BK);
        cp_commit();
    }

    float acc[4][4][4];
#pragma unroll
    for (int mi = 0; mi < 4; mi++)
#pragma unroll
        for (int nj = 0; nj < 4; nj++)
#pragma unroll
            for (int q = 0; q < 4; q++) acc[mi][nj][q] = 0.0f;

    const int ar = warp_m * 64 + (lane & 15);
    const int br = warp_n * 32 + (lane & 15);
    const int kgrp = lane >> 4;

#pragma unroll 1
    for (int it = 0; it < NT; ++it) {
        cp_wait<STAGES - 2>();
        __syncthreads();   // stage(it) ready; all warps done with old buffer

        if (it + STAGES - 1 < NT)
            LOAD_STAGE(sb + ((it + STAGES - 1) & (STAGES - 1)) * STAGE_B,
                       (it + STAGES - 1) * BK);
        cp_commit();

        const uint32_t stg = sb + (it & (STAGES - 1)) * STAGE_B;

        // hoist ALL B fragments for this 32-K tile (4 x ldsm4 = 16 regs)
        uint32_t bfr[4][4];
#pragma unroll
        for (int g = 0; g < 2; g++)
#pragma unroll
            for (int ni = 0; ni < 2; ni++)
                ldsm4(bfr[g * 2 + ni],
                      stg + TILE_B + tile_off(br + ni * 16, g * 2 + kgrp));

        // A fragments: 4 pipeline steps of (g, mi-pair), double-buffered
        uint32_t af[2][2][4];
#pragma unroll
        for (int q = 0; q < 2; q++)
            ldsm4(af[0][q], stg + tile_off(ar + q * 16, kgrp));   // (g=0,mp=0)

#pragma unroll
        for (int s = 0; s < 4; s++) {
            const int g = s >> 1, mp = s & 1, buf = s & 1;
            if (s < 3) {
                const int ng = (s + 1) >> 1, nmp = (s + 1) & 1;
#pragma unroll
                for (int q = 0; q < 2; q++)
                    ldsm4(af[buf ^ 1][q],
                          stg + tile_off(ar + (nmp * 2 + q) * 16, ng * 2 + kgrp));
            }
#pragma unroll
            for (int q = 0; q < 2; q++) {
                const int mi = mp * 2 + q;
#pragma unroll
                for (int nj = 0; nj < 4; nj++) {
                    const int ni = nj >> 1, sub = nj & 1;
                    mma_f16(acc[mi][nj], af[buf][q],
                            bfr[g * 2 + ni][sub], bfr[g * 2 + ni][sub + 2]);
                }
            }
        }
    }

    // epilogue: always write (zeros when gate is off / NT==0)
    const int crow = m0 + warp_m * 64 + (lane >> 2);
    const int ccol = n0 + warp_n * 32 + (lane & 3) * 2;
#pragma unroll
    for (int mi = 0; mi < 4; mi++) {
#pragma unroll
        for (int nj = 0; nj < 4; nj++) {
            float* p0 = C + (size_t)(crow + mi * 16) * NDIM + ccol + nj * 8;
            float* p1 = p0 + (size_t)8 * NDIM;
            *(float2*)p0 = make_float2(acc[mi][nj][0], acc[mi][nj][1]);
            *(float2*)p1 = make_float2(acc[mi][nj][2], acc[mi][nj][3]);
        }
    }
#undef LOAD_STAGE
}

// ---------------------------------------------------------------------------
// Launch
// ---------------------------------------------------------------------------
extern "C" void kernel_launch(void* const* d_in, const int* in_sizes, int n_in,
                              void* d_out, int out_size) {
    const float* x     = (const float*)d_in[0];
    const float* w     = (const float*)d_in[1];
    const void*  masks = d_in[2];
    const void*  perm  = d_in[3];
    float*       out   = (float*)d_out;

    cudaFuncSetAttribute(gemm_mma_kernel,
                         cudaFuncAttributeMaxDynamicSharedMemorySize, SMEM_TOTAL);

    prep_select_kernel<<<NPREP + 1, 1024>>>(x, perm, masks);
    convert_kernel<<<((MDIM + NDIM) * 1024) / 256, 256>>>(x, w);

    dim3 grid(NDIM / BN, MDIM / BM);   // (32, 32)
    gemm_mma_kernel<<<grid, 256, SMEM_TOTAL>>>(out);
}